// round 1
// baseline (speedup 1.0000x reference)
#include <cuda_runtime.h>
#include <math.h>

#define D_MODEL 1024
#define NHEAD   16
#define HDIM    64
#define BATCH   2
#define SEQ     2048
#define MTOT    (BATCH*SEQ)          // 4096
#define NQKV    (3*D_MODEL)          // 3072

// ---------------- scratch (static device globals; no allocation) ----------
__device__ float g_q[BATCH*NHEAD*SEQ*HDIM];     // 16 MB, [B,H,T,Dh]
__device__ float g_k[BATCH*NHEAD*SEQ*HDIM];     // 16 MB
__device__ float g_v[BATCH*NHEAD*SEQ*HDIM];     // 16 MB
__device__ float g_attn[MTOT*D_MODEL];          // 16 MB, [B,T,C]

// ===========================================================================
// GEMM 1: qkv = x @ w_qkv + b_qkv, scattered into g_q/g_k/g_v [B,H,T,Dh]
// A [4096,1024] row-major, B [1024,3072] row-major.
// 128x128x16 tile, 256 threads, 8x8 per thread.
// ===========================================================================
__global__ __launch_bounds__(256) void qkv_gemm_kernel(
    const float* __restrict__ x,
    const float* __restrict__ w,
    const float* __restrict__ bias)
{
    const int K = D_MODEL;
    const int N = NQKV;
    __shared__ float As[16][132];   // [k][m], padded
    __shared__ float Bs[16][128];   // [k][n]

    const int tid = threadIdx.x;
    const int tx = tid & 15;        // 0..15
    const int ty = tid >> 4;        // 0..15
    const int m0 = blockIdx.y * 128;
    const int n0 = blockIdx.x * 128;

    const int aRow = tid >> 2;      // 0..63
    const int aC4  = tid & 3;       // 0..3
    const int bRow = tid >> 5;      // 0..7
    const int bC4  = tid & 31;      // 0..31

    float acc[8][8];
    #pragma unroll
    for (int i = 0; i < 8; i++)
        #pragma unroll
        for (int j = 0; j < 8; j++) acc[i][j] = 0.f;

    for (int k0 = 0; k0 < K; k0 += 16) {
        #pragma unroll
        for (int r = 0; r < 2; r++) {
            int row = aRow + r*64;
            float4 v = *(const float4*)(x + (m0+row)*K + k0 + aC4*4);
            As[aC4*4+0][row] = v.x;
            As[aC4*4+1][row] = v.y;
            As[aC4*4+2][row] = v.z;
            As[aC4*4+3][row] = v.w;
        }
        #pragma unroll
        for (int r = 0; r < 2; r++) {
            int row = bRow + r*8;
            *(float4*)(&Bs[row][bC4*4]) =
                *(const float4*)(w + (k0+row)*N + n0 + bC4*4);
        }
        __syncthreads();

        #pragma unroll
        for (int k = 0; k < 16; k++) {
            float a[8], b[8];
            *(float4*)(a)   = *(const float4*)(&As[k][ty*8]);
            *(float4*)(a+4) = *(const float4*)(&As[k][ty*8+4]);
            *(float4*)(b)   = *(const float4*)(&Bs[k][tx*8]);
            *(float4*)(b+4) = *(const float4*)(&Bs[k][tx*8+4]);
            #pragma unroll
            for (int i = 0; i < 8; i++)
                #pragma unroll
                for (int j = 0; j < 8; j++)
                    acc[i][j] = fmaf(a[i], b[j], acc[i][j]);
        }
        __syncthreads();
    }

    // Epilogue: add bias, scatter into q/k/v [B,H,T,Dh]
    #pragma unroll
    for (int i = 0; i < 8; i++) {
        int m = m0 + ty*8 + i;
        int bb = m / SEQ;
        int t  = m % SEQ;
        #pragma unroll
        for (int j = 0; j < 8; j++) {
            int n = n0 + tx*8 + j;
            float val = acc[i][j] + bias[n];
            int sec = n >> 10;            // 0=q,1=k,2=v
            int h   = (n & 1023) >> 6;
            int d   = n & 63;
            float* dst = (sec == 0) ? g_q : (sec == 1) ? g_k : g_v;
            dst[((bb*NHEAD + h)*SEQ + t)*HDIM + d] = val;
        }
    }
}

// ===========================================================================
// Flash attention: per (q-tile 64, head, batch). fp32, online softmax.
// 256 threads: thread = (row = tid/4, colgroup = tid%4 -> 16 cols).
// ===========================================================================
#define QS_STRIDE 68
#define KT_STRIDE 68
#define SS_STRIDE 68
#define VS_STRIDE 64
// floats: Qs 64*68 + Kt 64*68 + Ss 64*68 + Vs 64*64
#define FLASH_SMEM_FLOATS (64*68*3 + 64*64)
#define FLASH_SMEM_BYTES  (FLASH_SMEM_FLOATS*4)

__global__ __launch_bounds__(256) void flash_attn_kernel()
{
    extern __shared__ float sm[];
    float* Qs = sm;                      // [t][d]  stride 68
    float* Kt = Qs + 64*QS_STRIDE;       // [d][t]  stride 68
    float* Ss = Kt + 64*KT_STRIDE;       // [row][col] stride 68
    float* Vs = Ss + 64*SS_STRIDE;       // [t][d]  stride 64

    const int tid = threadIdx.x;
    const int row = tid >> 2;            // 0..63
    const int cg  = tid & 3;             // 0..3
    const int c0  = cg * 16;

    const int qt = blockIdx.x;
    const int h  = blockIdx.y;
    const int bb = blockIdx.z;

    const float* qptr  = g_q + ((bb*NHEAD + h)*SEQ + qt*64)*HDIM;
    const float* kbase = g_k + (bb*NHEAD + h)*SEQ*HDIM;
    const float* vbase = g_v + (bb*NHEAD + h)*SEQ*HDIM;

    // load Q tile (64x64) into Qs
    for (int i4 = tid; i4 < 1024; i4 += 256) {
        int t = i4 >> 4, d4 = i4 & 15;
        *(float4*)(Qs + t*QS_STRIDE + d4*4) = *(const float4*)(qptr + t*64 + d4*4);
    }

    float mrow = -1e30f;
    float lrow = 0.f;
    float o[16];
    #pragma unroll
    for (int c = 0; c < 16; c++) o[c] = 0.f;

    const float scale = 0.125f;   // 1/sqrt(64)

    for (int kt = 0; kt < SEQ/64; kt++) {
        const float* kp = kbase + kt*64*HDIM;
        const float* vp = vbase + kt*64*HDIM;

        // load K transposed [d][t]
        for (int i = tid; i < 4096; i += 256) {
            int t = i >> 6, d = i & 63;
            Kt[d*KT_STRIDE + t] = kp[i];
        }
        // load V direct [t][d]
        for (int i4 = tid; i4 < 1024; i4 += 256) {
            int t = i4 >> 4, d4 = i4 & 15;
            *(float4*)(Vs + t*VS_STRIDE + d4*4) = *(const float4*)(vp + t*64 + d4*4);
        }
        __syncthreads();

        // S = Q K^T (this thread: row x [c0, c0+16))
        float s[16];
        #pragma unroll
        for (int j = 0; j < 16; j++) s[j] = 0.f;

        #pragma unroll 8
        for (int d = 0; d < 64; d++) {
            float q = Qs[row*QS_STRIDE + d];
            const float4* kk = (const float4*)(Kt + d*KT_STRIDE + c0);
            float4 k0v = kk[0], k1v = kk[1], k2v = kk[2], k3v = kk[3];
            s[0]  = fmaf(q, k0v.x, s[0]);  s[1]  = fmaf(q, k0v.y, s[1]);
            s[2]  = fmaf(q, k0v.z, s[2]);  s[3]  = fmaf(q, k0v.w, s[3]);
            s[4]  = fmaf(q, k1v.x, s[4]);  s[5]  = fmaf(q, k1v.y, s[5]);
            s[6]  = fmaf(q, k1v.z, s[6]);  s[7]  = fmaf(q, k1v.w, s[7]);
            s[8]  = fmaf(q, k2v.x, s[8]);  s[9]  = fmaf(q, k2v.y, s[9]);
            s[10] = fmaf(q, k2v.z, s[10]); s[11] = fmaf(q, k2v.w, s[11]);
            s[12] = fmaf(q, k3v.x, s[12]); s[13] = fmaf(q, k3v.y, s[13]);
            s[14] = fmaf(q, k3v.z, s[14]); s[15] = fmaf(q, k3v.w, s[15]);
        }

        // online softmax
        float mt = -1e30f;
        #pragma unroll
        for (int j = 0; j < 16; j++) { s[j] *= scale; mt = fmaxf(mt, s[j]); }
        mt = fmaxf(mt, __shfl_xor_sync(0xffffffffu, mt, 1));
        mt = fmaxf(mt, __shfl_xor_sync(0xffffffffu, mt, 2));

        float mnew = fmaxf(mrow, mt);
        float corr = __expf(mrow - mnew);
        mrow = mnew;

        float rs = 0.f;
        #pragma unroll
        for (int j = 0; j < 16; j++) {
            s[j] = __expf(s[j] - mnew);
            rs += s[j];
        }
        rs += __shfl_xor_sync(0xffffffffu, rs, 1);
        rs += __shfl_xor_sync(0xffffffffu, rs, 2);
        lrow = lrow * corr + rs;

        #pragma unroll
        for (int c = 0; c < 16; c++) o[c] *= corr;

        // write P to Ss (only own warp reads these rows)
        *(float4*)(Ss + row*SS_STRIDE + c0 + 0)  = make_float4(s[0], s[1], s[2], s[3]);
        *(float4*)(Ss + row*SS_STRIDE + c0 + 4)  = make_float4(s[4], s[5], s[6], s[7]);
        *(float4*)(Ss + row*SS_STRIDE + c0 + 8)  = make_float4(s[8], s[9], s[10], s[11]);
        *(float4*)(Ss + row*SS_STRIDE + c0 + 12) = make_float4(s[12], s[13], s[14], s[15]);
        __syncwarp();

        // O += P @ V   (this thread: row x [c0, c0+16) of V columns)
        #pragma unroll 8
        for (int j = 0; j < 64; j++) {
            float p = Ss[row*SS_STRIDE + j];
            const float4* vv = (const float4*)(Vs + j*VS_STRIDE + c0);
            float4 v0 = vv[0], v1 = vv[1], v2 = vv[2], v3 = vv[3];
            o[0]  = fmaf(p, v0.x, o[0]);  o[1]  = fmaf(p, v0.y, o[1]);
            o[2]  = fmaf(p, v0.z, o[2]);  o[3]  = fmaf(p, v0.w, o[3]);
            o[4]  = fmaf(p, v1.x, o[4]);  o[5]  = fmaf(p, v1.y, o[5]);
            o[6]  = fmaf(p, v1.z, o[6]);  o[7]  = fmaf(p, v1.w, o[7]);
            o[8]  = fmaf(p, v2.x, o[8]);  o[9]  = fmaf(p, v2.y, o[9]);
            o[10] = fmaf(p, v2.z, o[10]); o[11] = fmaf(p, v2.w, o[11]);
            o[12] = fmaf(p, v3.x, o[12]); o[13] = fmaf(p, v3.y, o[13]);
            o[14] = fmaf(p, v3.z, o[14]); o[15] = fmaf(p, v3.w, o[15]);
        }
        __syncthreads();   // Vs/Kt reused next iteration
    }

    // epilogue: normalize, write to g_attn [B,T,C] with C = (h, d)
    float inv = 1.0f / lrow;
    float* dst = g_attn + (bb*SEQ + qt*64 + row)*D_MODEL + h*64 + c0;
    *(float4*)(dst + 0)  = make_float4(o[0]*inv,  o[1]*inv,  o[2]*inv,  o[3]*inv);
    *(float4*)(dst + 4)  = make_float4(o[4]*inv,  o[5]*inv,  o[6]*inv,  o[7]*inv);
    *(float4*)(dst + 8)  = make_float4(o[8]*inv,  o[9]*inv,  o[10]*inv, o[11]*inv);
    *(float4*)(dst + 12) = make_float4(o[12]*inv, o[13]*inv, o[14]*inv, o[15]*inv);
}

// ===========================================================================
// GEMM 3: out = attn @ w_out + b_out   [4096,1024] @ [1024,1024]
// ===========================================================================
__global__ __launch_bounds__(256) void out_gemm_kernel(
    const float* __restrict__ w,
    const float* __restrict__ bias,
    float* __restrict__ out)
{
    const int K = D_MODEL;
    const int N = D_MODEL;
    const float* __restrict__ A = g_attn;

    __shared__ float As[16][132];
    __shared__ float Bs[16][128];

    const int tid = threadIdx.x;
    const int tx = tid & 15;
    const int ty = tid >> 4;
    const int m0 = blockIdx.y * 128;
    const int n0 = blockIdx.x * 128;

    const int aRow = tid >> 2;
    const int aC4  = tid & 3;
    const int bRow = tid >> 5;
    const int bC4  = tid & 31;

    float acc[8][8];
    #pragma unroll
    for (int i = 0; i < 8; i++)
        #pragma unroll
        for (int j = 0; j < 8; j++) acc[i][j] = 0.f;

    for (int k0 = 0; k0 < K; k0 += 16) {
        #pragma unroll
        for (int r = 0; r < 2; r++) {
            int row = aRow + r*64;
            float4 v = *(const float4*)(A + (m0+row)*K + k0 + aC4*4);
            As[aC4*4+0][row] = v.x;
            As[aC4*4+1][row] = v.y;
            As[aC4*4+2][row] = v.z;
            As[aC4*4+3][row] = v.w;
        }
        #pragma unroll
        for (int r = 0; r < 2; r++) {
            int row = bRow + r*8;
            *(float4*)(&Bs[row][bC4*4]) =
                *(const float4*)(w + (k0+row)*N + n0 + bC4*4);
        }
        __syncthreads();

        #pragma unroll
        for (int k = 0; k < 16; k++) {
            float a[8], b[8];
            *(float4*)(a)   = *(const float4*)(&As[k][ty*8]);
            *(float4*)(a+4) = *(const float4*)(&As[k][ty*8+4]);
            *(float4*)(b)   = *(const float4*)(&Bs[k][tx*8]);
            *(float4*)(b+4) = *(const float4*)(&Bs[k][tx*8+4]);
            #pragma unroll
            for (int i = 0; i < 8; i++)
                #pragma unroll
                for (int j = 0; j < 8; j++)
                    acc[i][j] = fmaf(a[i], b[j], acc[i][j]);
        }
        __syncthreads();
    }

    #pragma unroll
    for (int i = 0; i < 8; i++) {
        int m = m0 + ty*8 + i;
        #pragma unroll
        for (int j = 0; j < 8; j += 4) {
            int n = n0 + tx*8 + j;
            float4 v;
            v.x = acc[i][j+0] + bias[n+0];
            v.y = acc[i][j+1] + bias[n+1];
            v.z = acc[i][j+2] + bias[n+2];
            v.w = acc[i][j+3] + bias[n+3];
            *(float4*)(out + m*N + n) = v;
        }
    }
}

// ===========================================================================
extern "C" void kernel_launch(void* const* d_in, const int* in_sizes, int n_in,
                              void* d_out, int out_size)
{
    const float* x     = (const float*)d_in[0];
    const float* w_qkv = (const float*)d_in[1];
    const float* b_qkv = (const float*)d_in[2];
    const float* w_out = (const float*)d_in[3];
    const float* b_out = (const float*)d_in[4];
    float* out = (float*)d_out;

    (void)in_sizes; (void)n_in; (void)out_size;

    cudaFuncSetAttribute(flash_attn_kernel,
                         cudaFuncAttributeMaxDynamicSharedMemorySize,
                         FLASH_SMEM_BYTES);

    // 1) QKV GEMM + bias + scatter
    {
        dim3 grid(NQKV/128, MTOT/128);   // (24, 32)
        qkv_gemm_kernel<<<grid, 256>>>(x, w_qkv, b_qkv);
    }
    // 2) flash attention
    {
        dim3 grid(SEQ/64, NHEAD, BATCH); // (32, 16, 2)
        flash_attn_kernel<<<grid, 256, FLASH_SMEM_BYTES>>>();
    }
    // 3) output GEMM + bias
    {
        dim3 grid(D_MODEL/128, MTOT/128); // (8, 32)
        out_gemm_kernel<<<grid, 256>>>(w_out, b_out, out);
    }
}

// round 2
// speedup vs baseline: 2.8119x; 2.8119x over previous
#include <cuda_runtime.h>
#include <math.h>

#define D_MODEL 1024
#define NHEAD   16
#define HDIM    64
#define BATCH   2
#define SEQ     2048
#define MTOT    (BATCH*SEQ)          // 4096
#define NQKV    (3*D_MODEL)          // 3072

// ---------------- scratch (static device globals; no allocation) ----------
// g_q, g_k stored TRANSPOSED: [B,H,Dh,T].  g_v stored [B,H,T,Dh].
__device__ float g_q[BATCH*NHEAD*HDIM*SEQ];
__device__ float g_k[BATCH*NHEAD*HDIM*SEQ];
__device__ float g_v[BATCH*NHEAD*SEQ*HDIM];
__device__ float g_attn[MTOT*D_MODEL];          // [B,T,C]

// ===========================================================================
// GEMM 1: qkv = x @ w_qkv + b_qkv, scattered into g_q/g_k (transposed) / g_v
// 128x128x16 tile, 256 threads, 8x8 per thread.
// ===========================================================================
__global__ __launch_bounds__(256,2) void qkv_gemm_kernel(
    const float* __restrict__ x,
    const float* __restrict__ w,
    const float* __restrict__ bias)
{
    const int K = D_MODEL;
    const int N = NQKV;
    __shared__ float As[16][132];   // [k][m], padded
    __shared__ float Bs[16][128];   // [k][n]

    const int tid = threadIdx.x;
    const int tx = tid & 15;        // 0..15
    const int ty = tid >> 4;        // 0..15
    const int m0 = blockIdx.y * 128;
    const int n0 = blockIdx.x * 128;

    const int aRow = tid >> 2;      // 0..63
    const int aC4  = tid & 3;       // 0..3
    const int bRow = tid >> 5;      // 0..7
    const int bC4  = tid & 31;      // 0..31

    float acc[8][8];
    #pragma unroll
    for (int i = 0; i < 8; i++)
        #pragma unroll
        for (int j = 0; j < 8; j++) acc[i][j] = 0.f;

    for (int k0 = 0; k0 < K; k0 += 16) {
        #pragma unroll
        for (int r = 0; r < 2; r++) {
            int row = aRow + r*64;
            float4 v = *(const float4*)(x + (m0+row)*K + k0 + aC4*4);
            As[aC4*4+0][row] = v.x;
            As[aC4*4+1][row] = v.y;
            As[aC4*4+2][row] = v.z;
            As[aC4*4+3][row] = v.w;
        }
        #pragma unroll
        for (int r = 0; r < 2; r++) {
            int row = bRow + r*8;
            *(float4*)(&Bs[row][bC4*4]) =
                *(const float4*)(w + (k0+row)*N + n0 + bC4*4);
        }
        __syncthreads();

        #pragma unroll
        for (int k = 0; k < 16; k++) {
            float a[8], b[8];
            *(float4*)(a)   = *(const float4*)(&As[k][ty*8]);
            *(float4*)(a+4) = *(const float4*)(&As[k][ty*8+4]);
            *(float4*)(b)   = *(const float4*)(&Bs[k][tx*8]);
            *(float4*)(b+4) = *(const float4*)(&Bs[k][tx*8+4]);
            #pragma unroll
            for (int i = 0; i < 8; i++)
                #pragma unroll
                for (int j = 0; j < 8; j++)
                    acc[i][j] = fmaf(a[i], b[j], acc[i][j]);
        }
        __syncthreads();
    }

    // Epilogue: add bias, scatter. Q,K transposed [B,H,Dh,T]; V direct.
    #pragma unroll
    for (int i = 0; i < 8; i++) {
        int m = m0 + ty*8 + i;
        int bb = m / SEQ;
        int t  = m % SEQ;
        #pragma unroll
        for (int j = 0; j < 8; j++) {
            int n = n0 + tx*8 + j;
            float val = acc[i][j] + bias[n];
            int sec = n >> 10;            // 0=q,1=k,2=v
            int h   = (n & 1023) >> 6;
            int d   = n & 63;
            int bh  = bb*NHEAD + h;
            if (sec == 0)
                g_q[((size_t)bh*HDIM + d)*SEQ + t] = val;
            else if (sec == 1)
                g_k[((size_t)bh*HDIM + d)*SEQ + t] = val;
            else
                g_v[((size_t)bh*SEQ + t)*HDIM + d] = val;
        }
    }
}

// ===========================================================================
// Flash attention, GEMM-style register blocking.
// Q tile 128 rows, K tile 64 cols. 256 threads: ty=tid/16 (rows), tx=tid%16.
// Thread owns S[8x4] (rows r0..r0+7, cols c0..c0+3) and O[8x4]
// (rows r0..r0+7, dims c0..c0+3).
// ===========================================================================
#define QTILE 128
#define KTILE 64
// smem layout (floats):
//   Qs [64][132]  (d, t)   offset 0        size 8448
//   Kt [64][68]   (d, c)   offset 8448     size 4352
//   Vs [64][68]   (c, d)   offset 12800    size 4352
//   Ps [128][68]  (r, c)   offset 17152    size 8704
#define FLASH_SMEM_FLOATS 25856
#define FLASH_SMEM_BYTES  (FLASH_SMEM_FLOATS*4)

__global__ __launch_bounds__(256,2) void flash_attn_kernel()
{
    extern __shared__ float sm[];
    float* Qs = sm;            // [d][t] stride 132
    float* Kt = sm + 8448;     // [d][c] stride 68
    float* Vs = sm + 12800;    // [c][d] stride 68
    float* Ps = sm + 17152;    // [r][c] stride 68

    const int tid = threadIdx.x;
    const int tx  = tid & 15;
    const int ty  = tid >> 4;
    const int r0  = ty * 8;
    const int c0  = tx * 4;

    const int qt = blockIdx.x;
    const int h  = blockIdx.y;
    const int bb = blockIdx.z;
    const int bh = bb*NHEAD + h;

    const float* qT = g_q + (size_t)bh*HDIM*SEQ + qt*QTILE;  // + d*SEQ + t
    const float* kT = g_k + (size_t)bh*HDIM*SEQ;             // + d*SEQ + c
    const float* vb = g_v + (size_t)bh*SEQ*HDIM;             // + c*HDIM + d

    const float scale = 0.125f;   // 1/sqrt(64), folded into Q

    // load Q tile [d][t], pre-scaled
    #pragma unroll
    for (int i4 = tid; i4 < 64*32; i4 += 256) {
        int d = i4 >> 5, t4 = i4 & 31;
        float4 v = *(const float4*)(qT + (size_t)d*SEQ + t4*4);
        v.x *= scale; v.y *= scale; v.z *= scale; v.w *= scale;
        *(float4*)(Qs + d*132 + t4*4) = v;
    }

    float m[8], l[8], o[8][4];
    #pragma unroll
    for (int i = 0; i < 8; i++) {
        m[i] = -1e30f; l[i] = 0.f;
        #pragma unroll
        for (int j = 0; j < 4; j++) o[i][j] = 0.f;
    }

    for (int kt = 0; kt < SEQ/KTILE; kt++) {
        __syncthreads();   // protect Kt/Vs reuse from previous iteration

        // load K^T tile [d][c]  (coalesced: g_k is [Dh][T])
        for (int i4 = tid; i4 < 64*16; i4 += 256) {
            int d = i4 >> 4, t4 = i4 & 15;
            *(float4*)(Kt + d*68 + t4*4) =
                *(const float4*)(kT + (size_t)d*SEQ + kt*KTILE + t4*4);
        }
        // load V tile [c][d]
        for (int i4 = tid; i4 < 64*16; i4 += 256) {
            int c = i4 >> 4, d4 = i4 & 15;
            *(float4*)(Vs + c*68 + d4*4) =
                *(const float4*)(vb + (size_t)(kt*KTILE + c)*HDIM + d4*4);
        }
        __syncthreads();

        // ---- S = (Q*scale) K^T : per-thread 8x4 ----
        float s[8][4];
        #pragma unroll
        for (int i = 0; i < 8; i++)
            #pragma unroll
            for (int j = 0; j < 4; j++) s[i][j] = 0.f;

        #pragma unroll 16
        for (int d = 0; d < 64; d++) {
            float a[8];
            *(float4*)(a)   = *(const float4*)(Qs + d*132 + r0);
            *(float4*)(a+4) = *(const float4*)(Qs + d*132 + r0 + 4);
            float4 kv = *(const float4*)(Kt + d*68 + c0);
            #pragma unroll
            for (int i = 0; i < 8; i++) {
                s[i][0] = fmaf(a[i], kv.x, s[i][0]);
                s[i][1] = fmaf(a[i], kv.y, s[i][1]);
                s[i][2] = fmaf(a[i], kv.z, s[i][2]);
                s[i][3] = fmaf(a[i], kv.w, s[i][3]);
            }
        }

        // ---- online softmax (row reductions across 16 tx lanes) ----
        #pragma unroll
        for (int i = 0; i < 8; i++) {
            float mt = fmaxf(fmaxf(s[i][0], s[i][1]), fmaxf(s[i][2], s[i][3]));
            mt = fmaxf(mt, __shfl_xor_sync(0xffffffffu, mt, 1));
            mt = fmaxf(mt, __shfl_xor_sync(0xffffffffu, mt, 2));
            mt = fmaxf(mt, __shfl_xor_sync(0xffffffffu, mt, 4));
            mt = fmaxf(mt, __shfl_xor_sync(0xffffffffu, mt, 8));

            float mnew = fmaxf(m[i], mt);
            float corr = __expf(m[i] - mnew);
            m[i] = mnew;

            s[i][0] = __expf(s[i][0] - mnew);
            s[i][1] = __expf(s[i][1] - mnew);
            s[i][2] = __expf(s[i][2] - mnew);
            s[i][3] = __expf(s[i][3] - mnew);
            float rs = (s[i][0] + s[i][1]) + (s[i][2] + s[i][3]);
            rs += __shfl_xor_sync(0xffffffffu, rs, 1);
            rs += __shfl_xor_sync(0xffffffffu, rs, 2);
            rs += __shfl_xor_sync(0xffffffffu, rs, 4);
            rs += __shfl_xor_sync(0xffffffffu, rs, 8);
            l[i] = l[i]*corr + rs;

            o[i][0] *= corr; o[i][1] *= corr; o[i][2] *= corr; o[i][3] *= corr;

            *(float4*)(Ps + (r0+i)*68 + c0) =
                make_float4(s[i][0], s[i][1], s[i][2], s[i][3]);
        }
        __syncwarp();   // P rows r0..r0+7 fully written by this half-warp group

        // ---- O += P @ V : per-thread rows r0..r0+7, dims c0..c0+3 ----
        #pragma unroll 8
        for (int c4 = 0; c4 < 16; c4++) {
            float4 v0 = *(const float4*)(Vs + (c4*4+0)*68 + c0);
            float4 v1 = *(const float4*)(Vs + (c4*4+1)*68 + c0);
            float4 v2 = *(const float4*)(Vs + (c4*4+2)*68 + c0);
            float4 v3 = *(const float4*)(Vs + (c4*4+3)*68 + c0);
            #pragma unroll
            for (int i = 0; i < 8; i++) {
                float4 p = *(const float4*)(Ps + (r0+i)*68 + c4*4);
                o[i][0] = fmaf(p.x, v0.x, o[i][0]);
                o[i][1] = fmaf(p.x, v0.y, o[i][1]);
                o[i][2] = fmaf(p.x, v0.z, o[i][2]);
                o[i][3] = fmaf(p.x, v0.w, o[i][3]);
                o[i][0] = fmaf(p.y, v1.x, o[i][0]);
                o[i][1] = fmaf(p.y, v1.y, o[i][1]);
                o[i][2] = fmaf(p.y, v1.z, o[i][2]);
                o[i][3] = fmaf(p.y, v1.w, o[i][3]);
                o[i][0] = fmaf(p.z, v2.x, o[i][0]);
                o[i][1] = fmaf(p.z, v2.y, o[i][1]);
                o[i][2] = fmaf(p.z, v2.z, o[i][2]);
                o[i][3] = fmaf(p.z, v2.w, o[i][3]);
                o[i][0] = fmaf(p.w, v3.x, o[i][0]);
                o[i][1] = fmaf(p.w, v3.y, o[i][1]);
                o[i][2] = fmaf(p.w, v3.z, o[i][2]);
                o[i][3] = fmaf(p.w, v3.w, o[i][3]);
            }
        }
    }

    // epilogue: normalize, write [B,T,C] with C=(h,d)
    #pragma unroll
    for (int i = 0; i < 8; i++) {
        float inv = 1.0f / l[i];
        float* dst = g_attn + (size_t)(bb*SEQ + qt*QTILE + r0 + i)*D_MODEL + h*64 + c0;
        *(float4*)dst = make_float4(o[i][0]*inv, o[i][1]*inv, o[i][2]*inv, o[i][3]*inv);
    }
}

// ===========================================================================
// GEMM 3: out = attn @ w_out + b_out   [4096,1024] @ [1024,1024]
// ===========================================================================
__global__ __launch_bounds__(256,2) void out_gemm_kernel(
    const float* __restrict__ w,
    const float* __restrict__ bias,
    float* __restrict__ out)
{
    const int K = D_MODEL;
    const int N = D_MODEL;
    const float* __restrict__ A = g_attn;

    __shared__ float As[16][132];
    __shared__ float Bs[16][128];

    const int tid = threadIdx.x;
    const int tx = tid & 15;
    const int ty = tid >> 4;
    const int m0 = blockIdx.y * 128;
    const int n0 = blockIdx.x * 128;

    const int aRow = tid >> 2;
    const int aC4  = tid & 3;
    const int bRow = tid >> 5;
    const int bC4  = tid & 31;

    float acc[8][8];
    #pragma unroll
    for (int i = 0; i < 8; i++)
        #pragma unroll
        for (int j = 0; j < 8; j++) acc[i][j] = 0.f;

    for (int k0 = 0; k0 < K; k0 += 16) {
        #pragma unroll
        for (int r = 0; r < 2; r++) {
            int row = aRow + r*64;
            float4 v = *(const float4*)(A + (m0+row)*K + k0 + aC4*4);
            As[aC4*4+0][row] = v.x;
            As[aC4*4+1][row] = v.y;
            As[aC4*4+2][row] = v.z;
            As[aC4*4+3][row] = v.w;
        }
        #pragma unroll
        for (int r = 0; r < 2; r++) {
            int row = bRow + r*8;
            *(float4*)(&Bs[row][bC4*4]) =
                *(const float4*)(w + (k0+row)*N + n0 + bC4*4);
        }
        __syncthreads();

        #pragma unroll
        for (int k = 0; k < 16; k++) {
            float a[8], b[8];
            *(float4*)(a)   = *(const float4*)(&As[k][ty*8]);
            *(float4*)(a+4) = *(const float4*)(&As[k][ty*8+4]);
            *(float4*)(b)   = *(const float4*)(&Bs[k][tx*8]);
            *(float4*)(b+4) = *(const float4*)(&Bs[k][tx*8+4]);
            #pragma unroll
            for (int i = 0; i < 8; i++)
                #pragma unroll
                for (int j = 0; j < 8; j++)
                    acc[i][j] = fmaf(a[i], b[j], acc[i][j]);
        }
        __syncthreads();
    }

    #pragma unroll
    for (int i = 0; i < 8; i++) {
        int m = m0 + ty*8 + i;
        #pragma unroll
        for (int j = 0; j < 8; j += 4) {
            int n = n0 + tx*8 + j;
            float4 v;
            v.x = acc[i][j+0] + bias[n+0];
            v.y = acc[i][j+1] + bias[n+1];
            v.z = acc[i][j+2] + bias[n+2];
            v.w = acc[i][j+3] + bias[n+3];
            *(float4*)(out + m*N + n) = v;
        }
    }
}

// ===========================================================================
extern "C" void kernel_launch(void* const* d_in, const int* in_sizes, int n_in,
                              void* d_out, int out_size)
{
    const float* x     = (const float*)d_in[0];
    const float* w_qkv = (const float*)d_in[1];
    const float* b_qkv = (const float*)d_in[2];
    const float* w_out = (const float*)d_in[3];
    const float* b_out = (const float*)d_in[4];
    float* out = (float*)d_out;

    (void)in_sizes; (void)n_in; (void)out_size;

    cudaFuncSetAttribute(flash_attn_kernel,
                         cudaFuncAttributeMaxDynamicSharedMemorySize,
                         FLASH_SMEM_BYTES);

    // 1) QKV GEMM + bias + scatter (Q,K transposed)
    {
        dim3 grid(NQKV/128, MTOT/128);   // (24, 32)
        qkv_gemm_kernel<<<grid, 256>>>(x, w_qkv, b_qkv);
    }
    // 2) flash attention
    {
        dim3 grid(SEQ/QTILE, NHEAD, BATCH); // (16, 16, 2)
        flash_attn_kernel<<<grid, 256, FLASH_SMEM_BYTES>>>();
    }
    // 3) output GEMM + bias
    {
        dim3 grid(D_MODEL/128, MTOT/128); // (8, 32)
        out_gemm_kernel<<<grid, 256>>>(w_out, b_out, out);
    }
}